// round 3
// baseline (speedup 1.0000x reference)
#include <cuda_runtime.h>
#include <math.h>

#define Bsz 8
#define Ssz 2048
#define Fsz 256
#define Dsz 256

// Scratch for Q/K/V projections (alloc-free rule: __device__ globals)
__device__ float g_Q[Bsz * Ssz * Dsz];
__device__ float g_K[Bsz * Ssz * Dsz];
__device__ float g_V[Bsz * Ssz * Dsz];

// ---------------------------------------------------------------------------
// Kernel 1: fused QKV projection. Y = x @ W + b for W in {Wq,Wk,Wv} (blockIdx.z)
// Tiled GEMM: BM=64, BN=64, BK=16, 256 threads, 4x4 micro-tile per thread.
// ---------------------------------------------------------------------------
#define PBM 64
#define PBN 64
#define PBK 16

__global__ __launch_bounds__(256) void qkv_proj_kernel(
    const float* __restrict__ x,
    const float* __restrict__ Wq, const float* __restrict__ bq,
    const float* __restrict__ Wk, const float* __restrict__ bk,
    const float* __restrict__ Wv, const float* __restrict__ bv)
{
    const float* W;
    const float* bias;
    float* Y;
    if (blockIdx.z == 0)      { W = Wq; bias = bq; Y = g_Q; }
    else if (blockIdx.z == 1) { W = Wk; bias = bk; Y = g_K; }
    else                      { W = Wv; bias = bv; Y = g_V; }

    __shared__ float As[PBK][68];   // A transposed, padded (store conflicts)
    __shared__ float Bs[PBK][64];

    const int tid = threadIdx.x;
    const int m0 = blockIdx.x * PBM;
    const int n0 = blockIdx.y * PBN;
    const int ty = tid >> 4, tx = tid & 15;

    const int ra = tid >> 2, cq = (tid & 3) * 4;   // A loader
    const int kb = tid >> 4, nb = (tid & 15) * 4;  // B loader

    float acc[4][4];
#pragma unroll
    for (int i = 0; i < 4; i++)
#pragma unroll
        for (int j = 0; j < 4; j++) acc[i][j] = 0.f;

    for (int k0 = 0; k0 < Fsz; k0 += PBK) {
        float4 a = *(const float4*)(x + (size_t)(m0 + ra) * Fsz + k0 + cq);
        As[cq + 0][ra] = a.x; As[cq + 1][ra] = a.y;
        As[cq + 2][ra] = a.z; As[cq + 3][ra] = a.w;
        *(float4*)&Bs[kb][nb] =
            *(const float4*)(W + (size_t)(k0 + kb) * Dsz + n0 + nb);
        __syncthreads();

#pragma unroll
        for (int k = 0; k < PBK; k++) {
            float4 av  = *(const float4*)&As[k][ty * 4];
            float4 bv4 = *(const float4*)&Bs[k][tx * 4];
            float aa[4] = {av.x, av.y, av.z, av.w};
            float bb[4] = {bv4.x, bv4.y, bv4.z, bv4.w};
#pragma unroll
            for (int i = 0; i < 4; i++)
#pragma unroll
                for (int j = 0; j < 4; j++) acc[i][j] += aa[i] * bb[j];
        }
        __syncthreads();
    }

#pragma unroll
    for (int i = 0; i < 4; i++) {
        float4 o;
        o.x = acc[i][0] + bias[n0 + tx * 4 + 0];
        o.y = acc[i][1] + bias[n0 + tx * 4 + 1];
        o.z = acc[i][2] + bias[n0 + tx * 4 + 2];
        o.w = acc[i][3] + bias[n0 + tx * 4 + 3];
        *(float4*)(Y + (size_t)(m0 + ty * 4 + i) * Dsz + n0 + tx * 4) = o;
    }
}

// ---------------------------------------------------------------------------
// Kernel 2: flash attention. One CTA = (batch b, 64-row q tile). 256 threads.
// Q/K/V tiles in smem (padded rows to break 1024B-stride bank aliasing),
// online softmax, O accumulator in registers (64 f32/thread).
// ---------------------------------------------------------------------------
#define QTILE 64
#define KTILE 64
#define LDQ   260   // 256 + 4 pad (1040B rows -> 16B/row bank shift)
#define LDSS  68    // 64 + 4 pad
#define ATTN_SMEM_BYTES ((3 * 64 * LDQ + 64 * LDSS) * 4)  // 217088

__global__ __launch_bounds__(256) void attn_kernel(float* __restrict__ out)
{
    extern __shared__ float sm[];
    float* Qs = sm;                 // [64][LDQ]
    float* Ks = Qs + 64 * LDQ;      // [64][LDQ]
    float* Vs = Ks + 64 * LDQ;      // [64][LDQ]
    float* Ss = Vs + 64 * LDQ;      // [64][LDSS]

    const int b  = blockIdx.y;
    const int q0 = blockIdx.x * QTILE;
    const int tid = threadIdx.x;

    const float* Qg = g_Q + ((size_t)b * Ssz + q0) * Dsz;
    const float* Kg = g_K + (size_t)b * Ssz * Dsz;
    const float* Vg = g_V + (size_t)b * Ssz * Dsz;

    // Load Q tile (64 x 256 floats = 4096 float4, 16 per thread)
    for (int i = tid; i < QTILE * (Dsz / 4); i += 256) {
        int r = i >> 6;              // 64 float4 per row
        int c = (i & 63) * 4;
        *(float4*)&Qs[r * LDQ + c] = *(const float4*)(Qg + r * Dsz + c);
    }

    // S-compute mapping: strided 4x4 micro-tile (rows ty+16i, cols tx+16j)
    const int ty = tid >> 4, tx = tid & 15;
    // softmax / AV mapping: thread owns row rr, column segment c0..c0+63
    const int rr = tid >> 2, qq = tid & 3;
    const int c0 = qq * 64;

    float o[64];
#pragma unroll
    for (int i = 0; i < 64; i++) o[i] = 0.f;
    float mrow = -1e30f, lrow = 0.f;

    for (int j0 = 0; j0 < Ssz; j0 += KTILE) {
        __syncthreads();  // prev AV done (and Q load done on first iter)

        // Load K/V tiles
        for (int i = tid; i < KTILE * 64; i += 256) {
            int r = i >> 6;
            int c = (i & 63) * 4;
            *(float4*)&Ks[r * LDQ + c] = *(const float4*)(Kg + (size_t)(j0 + r) * Dsz + c);
            *(float4*)&Vs[r * LDQ + c] = *(const float4*)(Vg + (size_t)(j0 + r) * Dsz + c);
        }
        __syncthreads();

        // S = (Q @ K^T) / 16
        float acc[4][4];
#pragma unroll
        for (int i = 0; i < 4; i++)
#pragma unroll
            for (int j = 0; j < 4; j++) acc[i][j] = 0.f;

        for (int k4 = 0; k4 < Dsz / 4; k4++) {
            float4 qv[4], kv[4];
#pragma unroll
            for (int i = 0; i < 4; i++)
                qv[i] = *(const float4*)&Qs[(ty + 16 * i) * LDQ + k4 * 4];
#pragma unroll
            for (int j = 0; j < 4; j++)
                kv[j] = *(const float4*)&Ks[(tx + 16 * j) * LDQ + k4 * 4];
#pragma unroll
            for (int i = 0; i < 4; i++)
#pragma unroll
                for (int j = 0; j < 4; j++)
                    acc[i][j] += qv[i].x * kv[j].x + qv[i].y * kv[j].y
                               + qv[i].z * kv[j].z + qv[i].w * kv[j].w;
        }
#pragma unroll
        for (int i = 0; i < 4; i++)
#pragma unroll
            for (int j = 0; j < 4; j++)
                Ss[(ty + 16 * i) * LDSS + tx + 16 * j] = acc[i][j] * 0.0625f;
        __syncthreads();

        // Online softmax on row rr; this thread handles cols qq*16..qq*16+15.
        // The 4 threads of a row are consecutive lanes -> shfl_xor 1,2 combine.
        float tmax = -1e30f;
#pragma unroll
        for (int j = 0; j < 16; j++)
            tmax = fmaxf(tmax, Ss[rr * LDSS + qq * 16 + j]);
        tmax = fmaxf(tmax, __shfl_xor_sync(0xffffffffu, tmax, 1));
        tmax = fmaxf(tmax, __shfl_xor_sync(0xffffffffu, tmax, 2));

        float mnew  = fmaxf(mrow, tmax);
        float alpha = __expf(mrow - mnew);
        float psum  = 0.f;
#pragma unroll
        for (int j = 0; j < 16; j++) {
            float p = __expf(Ss[rr * LDSS + qq * 16 + j] - mnew);
            Ss[rr * LDSS + qq * 16 + j] = p;
            psum += p;
        }
        psum += __shfl_xor_sync(0xffffffffu, psum, 1);
        psum += __shfl_xor_sync(0xffffffffu, psum, 2);
        lrow = lrow * alpha + psum;
        mrow = mnew;
        __syncthreads();

        // O = O*alpha + P @ V  (thread owns row rr, cols c0..c0+63)
#pragma unroll
        for (int i = 0; i < 64; i++) o[i] *= alpha;
        for (int j = 0; j < KTILE; j++) {
            float p = Ss[rr * LDSS + j];
#pragma unroll
            for (int i4 = 0; i4 < 16; i4++) {
                float4 v = *(const float4*)&Vs[j * LDQ + c0 + i4 * 4];
                o[i4 * 4 + 0] += p * v.x;
                o[i4 * 4 + 1] += p * v.y;
                o[i4 * 4 + 2] += p * v.z;
                o[i4 * 4 + 3] += p * v.w;
            }
        }
    }

    const float inv = 1.f / lrow;
    float* og = out + ((size_t)b * Ssz + q0 + rr) * Dsz + c0;
#pragma unroll
    for (int i4 = 0; i4 < 16; i4++) {
        float4 v;
        v.x = o[i4 * 4 + 0] * inv;
        v.y = o[i4 * 4 + 1] * inv;
        v.z = o[i4 * 4 + 2] * inv;
        v.w = o[i4 * 4 + 3] * inv;
        *(float4*)(og + i4 * 4) = v;
    }
}

// ---------------------------------------------------------------------------
extern "C" void kernel_launch(void* const* d_in, const int* in_sizes, int n_in,
                              void* d_out, int out_size)
{
    const float* x  = (const float*)d_in[0];
    const float* Wq = (const float*)d_in[1];
    const float* bq = (const float*)d_in[2];
    const float* Wk = (const float*)d_in[3];
    const float* bk = (const float*)d_in[4];
    const float* Wv = (const float*)d_in[5];
    const float* bv = (const float*)d_in[6];
    float* out = (float*)d_out;

    cudaFuncSetAttribute(attn_kernel,
                         cudaFuncAttributeMaxDynamicSharedMemorySize,
                         ATTN_SMEM_BYTES);

    dim3 pg(Bsz * Ssz / PBM, Dsz / PBN, 3);
    qkv_proj_kernel<<<pg, 256>>>(x, Wq, bq, Wk, bk, Wv, bv);

    dim3 ag(Ssz / QTILE, Bsz);
    attn_kernel<<<ag, 256, ATTN_SMEM_BYTES>>>(out);
}

// round 4
// speedup vs baseline: 3.5132x; 3.5132x over previous
#include <cuda_runtime.h>
#include <math.h>

#define Bsz 8
#define Ssz 2048
#define Fsz 256
#define Dsz 256

// Scratch for Q/K/V projections (alloc-free rule: __device__ globals)
__device__ float g_Q[Bsz * Ssz * Dsz];
__device__ float g_K[Bsz * Ssz * Dsz];
__device__ float g_V[Bsz * Ssz * Dsz];

// ---------------------------------------------------------------------------
// Packed f32x2 helpers (Blackwell FFMA2 path — PTX-only, ptxas won't auto-fuse)
// ---------------------------------------------------------------------------
__device__ __forceinline__ unsigned long long pack2(float lo, float hi) {
    unsigned long long r;
    asm("mov.b64 %0, {%1,%2};" : "=l"(r) : "f"(lo), "f"(hi));
    return r;
}
__device__ __forceinline__ void unpack2(unsigned long long v, float& lo, float& hi) {
    asm("mov.b64 {%0,%1}, %2;" : "=f"(lo), "=f"(hi) : "l"(v));
}
__device__ __forceinline__ void fma2(unsigned long long& d,
                                     unsigned long long a, unsigned long long b) {
    asm("fma.rn.f32x2 %0, %1, %2, %0;" : "+l"(d) : "l"(a), "l"(b));
}
__device__ __forceinline__ unsigned long long mul2(unsigned long long a,
                                                   unsigned long long b) {
    unsigned long long r;
    asm("mul.rn.f32x2 %0, %1, %2;" : "=l"(r) : "l"(a), "l"(b));
    return r;
}

// ---------------------------------------------------------------------------
// Kernel 1: fused QKV projection (unchanged this round, ~120us)
// ---------------------------------------------------------------------------
#define PBM 64
#define PBN 64
#define PBK 16

__global__ __launch_bounds__(256) void qkv_proj_kernel(
    const float* __restrict__ x,
    const float* __restrict__ Wq, const float* __restrict__ bq,
    const float* __restrict__ Wk, const float* __restrict__ bk,
    const float* __restrict__ Wv, const float* __restrict__ bv)
{
    const float* W;
    const float* bias;
    float* Y;
    if (blockIdx.z == 0)      { W = Wq; bias = bq; Y = g_Q; }
    else if (blockIdx.z == 1) { W = Wk; bias = bk; Y = g_K; }
    else                      { W = Wv; bias = bv; Y = g_V; }

    __shared__ float As[PBK][68];
    __shared__ float Bs[PBK][64];

    const int tid = threadIdx.x;
    const int m0 = blockIdx.x * PBM;
    const int n0 = blockIdx.y * PBN;
    const int ty = tid >> 4, tx = tid & 15;

    const int ra = tid >> 2, cq = (tid & 3) * 4;
    const int kb = tid >> 4, nb = (tid & 15) * 4;

    float acc[4][4];
#pragma unroll
    for (int i = 0; i < 4; i++)
#pragma unroll
        for (int j = 0; j < 4; j++) acc[i][j] = 0.f;

    for (int k0 = 0; k0 < Fsz; k0 += PBK) {
        float4 a = *(const float4*)(x + (size_t)(m0 + ra) * Fsz + k0 + cq);
        As[cq + 0][ra] = a.x; As[cq + 1][ra] = a.y;
        As[cq + 2][ra] = a.z; As[cq + 3][ra] = a.w;
        *(float4*)&Bs[kb][nb] =
            *(const float4*)(W + (size_t)(k0 + kb) * Dsz + n0 + nb);
        __syncthreads();

#pragma unroll
        for (int k = 0; k < PBK; k++) {
            float4 av  = *(const float4*)&As[k][ty * 4];
            float4 bv4 = *(const float4*)&Bs[k][tx * 4];
            float aa[4] = {av.x, av.y, av.z, av.w};
            float bb[4] = {bv4.x, bv4.y, bv4.z, bv4.w};
#pragma unroll
            for (int i = 0; i < 4; i++)
#pragma unroll
                for (int j = 0; j < 4; j++) acc[i][j] += aa[i] * bb[j];
        }
        __syncthreads();
    }

#pragma unroll
    for (int i = 0; i < 4; i++) {
        float4 o;
        o.x = acc[i][0] + bias[n0 + tx * 4 + 0];
        o.y = acc[i][1] + bias[n0 + tx * 4 + 1];
        o.z = acc[i][2] + bias[n0 + tx * 4 + 2];
        o.w = acc[i][3] + bias[n0 + tx * 4 + 3];
        *(float4*)(Y + (size_t)(m0 + ty * 4 + i) * Dsz + n0 + tx * 4) = o;
    }
}

// ---------------------------------------------------------------------------
// Kernel 2: flash attention, restructured.
//  - S stored TRANSPOSED (Ss[col][row]) so PV is an 8x8 register-blocked
//    outer product: 4 LDS instr per warp per j (was 17).
//  - fma.rn.f32x2 packed accumulation in both QK and PV (halves FMA issue).
//  - per-row softmax stats (m, l, alpha) live in smem; softmax threads own
//    rows, PV threads own 8-row x 8-col tiles.
// ---------------------------------------------------------------------------
#define QTILE 64
#define KTILE 64
#define LDQ   260   // 256 + 4 pad
#define LDSS  68    // 64 + 4 pad (multiple of 4 for aligned float4 PV reads)
#define ATTN_SMEM_BYTES ((3 * 64 * LDQ + 64 * LDSS + 3 * 64) * 4)  // 217856

__global__ __launch_bounds__(256) void attn_kernel(float* __restrict__ out)
{
    extern __shared__ float sm[];
    float* Qs = sm;                  // [64][LDQ]  (pre-scaled by 1/16)
    float* Ks = Qs + 64 * LDQ;       // [64][LDQ]
    float* Vs = Ks + 64 * LDQ;       // [64][LDQ]
    float* Ss = Vs + 64 * LDQ;       // transposed: Ss[col*LDSS + row]
    float* sM = Ss + 64 * LDSS;      // [64] running max
    float* sL = sM + 64;             // [64] running sum
    float* sA = sL + 64;             // [64] alpha of current tile

    const int b   = blockIdx.y;
    const int q0  = blockIdx.x * QTILE;
    const int tid = threadIdx.x;

    const float* Qg = g_Q + ((size_t)b * Ssz + q0) * Dsz;
    const float* Kg = g_K + (size_t)b * Ssz * Dsz;
    const float* Vg = g_V + (size_t)b * Ssz * Dsz;

    if (tid < 64) { sM[tid] = -1e30f; sL[tid] = 0.f; }

    // Load Q tile, folding in the 1/sqrt(D) = 1/16 scale
    for (int i = tid; i < QTILE * (Dsz / 4); i += 256) {
        int r = i >> 6;
        int c = (i & 63) * 4;
        float4 a = *(const float4*)(Qg + r * Dsz + c);
        a.x *= 0.0625f; a.y *= 0.0625f; a.z *= 0.0625f; a.w *= 0.0625f;
        *(float4*)&Qs[r * LDQ + c] = a;
    }

    const int ty = tid >> 4, tx = tid & 15;   // QK: rows ty+16i, cols tx+16j
    const int rr = tid >> 2, qq = tid & 3;    // softmax: row rr, j-chunk qq
    const int tr = tid >> 5, tc = tid & 31;   // PV: rows tr*8.., cols tc*8..

    // O accumulator: 8 rows x 8 cols as 8x4 packed f32x2
    unsigned long long o2[32];
#pragma unroll
    for (int i = 0; i < 32; i++) o2[i] = 0ull;

    for (int j0 = 0; j0 < Ssz; j0 += KTILE) {
        __syncthreads();   // prev PV done with Vs/Ss/sA (Q load done, iter 0)

        // Load K/V tiles
        for (int i = tid; i < KTILE * 64; i += 256) {
            int r = i >> 6;
            int c = (i & 63) * 4;
            *(float4*)&Ks[r * LDQ + c] =
                *(const float4*)(Kg + (size_t)(j0 + r) * Dsz + c);
            *(float4*)&Vs[r * LDQ + c] =
                *(const float4*)(Vg + (size_t)(j0 + r) * Dsz + c);
        }
        __syncthreads();

        // ---- S^T = (Q/16 @ K^T)^T, packed f32x2 accumulation ----
        // acc2[i][0] = (S[ri][tx], S[ri][tx+16]); acc2[i][1] = (.., tx+32/48)
        unsigned long long acc2[4][2];
#pragma unroll
        for (int i = 0; i < 4; i++) { acc2[i][0] = 0ull; acc2[i][1] = 0ull; }

#pragma unroll 2
        for (int k4 = 0; k4 < Dsz / 4; k4++) {
            float qf[4][4], kf[4][4];
#pragma unroll
            for (int i = 0; i < 4; i++)
                *(float4*)qf[i] = *(const float4*)&Qs[(ty + 16 * i) * LDQ + k4 * 4];
#pragma unroll
            for (int j = 0; j < 4; j++)
                *(float4*)kf[j] = *(const float4*)&Ks[(tx + 16 * j) * LDQ + k4 * 4];
#pragma unroll
            for (int k = 0; k < 4; k++) {
                unsigned long long kp0 = pack2(kf[0][k], kf[1][k]);
                unsigned long long kp1 = pack2(kf[2][k], kf[3][k]);
#pragma unroll
                for (int i = 0; i < 4; i++) {
                    unsigned long long qd = pack2(qf[i][k], qf[i][k]);
                    fma2(acc2[i][0], qd, kp0);
                    fma2(acc2[i][1], qd, kp1);
                }
            }
        }
        // Store transposed: Ss[col][row]
#pragma unroll
        for (int i = 0; i < 4; i++) {
            int ri = ty + 16 * i;
            float s0, s1, s2, s3;
            unpack2(acc2[i][0], s0, s1);
            unpack2(acc2[i][1], s2, s3);
            Ss[(tx +  0) * LDSS + ri] = s0;
            Ss[(tx + 16) * LDSS + ri] = s1;
            Ss[(tx + 32) * LDSS + ri] = s2;
            Ss[(tx + 48) * LDSS + ri] = s3;
        }
        __syncthreads();

        // ---- online softmax on row rr (4 threads/row over j-chunks) ----
        {
            float tmax = -1e30f;
#pragma unroll
            for (int t = 0; t < 16; t++)
                tmax = fmaxf(tmax, Ss[(qq * 16 + t) * LDSS + rr]);
            tmax = fmaxf(tmax, __shfl_xor_sync(0xffffffffu, tmax, 1));
            tmax = fmaxf(tmax, __shfl_xor_sync(0xffffffffu, tmax, 2));

            float mold  = sM[rr];
            float mnew  = fmaxf(mold, tmax);
            float alpha = __expf(mold - mnew);
            float psum  = 0.f;
#pragma unroll
            for (int t = 0; t < 16; t++) {
                float p = __expf(Ss[(qq * 16 + t) * LDSS + rr] - mnew);
                Ss[(qq * 16 + t) * LDSS + rr] = p;
                psum += p;
            }
            psum += __shfl_xor_sync(0xffffffffu, psum, 1);
            psum += __shfl_xor_sync(0xffffffffu, psum, 2);
            if (qq == 0) {
                sL[rr] = sL[rr] * alpha + psum;
                sM[rr] = mnew;
                sA[rr] = alpha;
            }
        }
        __syncthreads();

        // ---- O = O*alpha + P @ V   (8x8 per thread, packed f32x2) ----
#pragma unroll
        for (int r8 = 0; r8 < 8; r8++) {
            float a = sA[tr * 8 + r8];
            unsigned long long ad = pack2(a, a);
#pragma unroll
            for (int c2 = 0; c2 < 4; c2++)
                o2[r8 * 4 + c2] = mul2(o2[r8 * 4 + c2], ad);
        }
#pragma unroll 2
        for (int j = 0; j < KTILE; j++) {
            float pf[8];
            *(float4*)(pf)     = *(const float4*)&Ss[j * LDSS + tr * 8];
            *(float4*)(pf + 4) = *(const float4*)&Ss[j * LDSS + tr * 8 + 4];
            ulonglong2 u0 = *(const ulonglong2*)&Vs[j * LDQ + tc * 8];
            ulonglong2 u1 = *(const ulonglong2*)&Vs[j * LDQ + tc * 8 + 4];
#pragma unroll
            for (int r8 = 0; r8 < 8; r8++) {
                unsigned long long pd = pack2(pf[r8], pf[r8]);
                fma2(o2[r8 * 4 + 0], pd, u0.x);
                fma2(o2[r8 * 4 + 1], pd, u0.y);
                fma2(o2[r8 * 4 + 2], pd, u1.x);
                fma2(o2[r8 * 4 + 3], pd, u1.y);
            }
        }
    }

    // ---- epilogue: normalize by 1/l and store ----
#pragma unroll
    for (int r8 = 0; r8 < 8; r8++) {
        float inv = 1.f / sL[tr * 8 + r8];
        float f[8];
        unpack2(o2[r8 * 4 + 0], f[0], f[1]);
        unpack2(o2[r8 * 4 + 1], f[2], f[3]);
        unpack2(o2[r8 * 4 + 2], f[4], f[5]);
        unpack2(o2[r8 * 4 + 3], f[6], f[7]);
        float* og = out + ((size_t)b * Ssz + q0 + tr * 8 + r8) * Dsz + tc * 8;
        float4 v0, v1;
        v0.x = f[0] * inv; v0.y = f[1] * inv; v0.z = f[2] * inv; v0.w = f[3] * inv;
        v1.x = f[4] * inv; v1.y = f[5] * inv; v1.z = f[6] * inv; v1.w = f[7] * inv;
        *(float4*)(og)     = v0;
        *(float4*)(og + 4) = v1;
    }
}

// ---------------------------------------------------------------------------
extern "C" void kernel_launch(void* const* d_in, const int* in_sizes, int n_in,
                              void* d_out, int out_size)
{
    const float* x  = (const float*)d_in[0];
    const float* Wq = (const float*)d_in[1];
    const float* bq = (const float*)d_in[2];
    const float* Wk = (const float*)d_in[3];
    const float* bk = (const float*)d_in[4];
    const float* Wv = (const float*)d_in[5];
    const float* bv = (const float*)d_in[6];
    float* out = (float*)d_out;

    cudaFuncSetAttribute(attn_kernel,
                         cudaFuncAttributeMaxDynamicSharedMemorySize,
                         ATTN_SMEM_BYTES);

    dim3 pg(Bsz * Ssz / PBM, Dsz / PBN, 3);
    qkv_proj_kernel<<<pg, 256>>>(x, Wq, bq, Wk, bk, Wv, bv);

    dim3 ag(Ssz / QTILE, Bsz);
    attn_kernel<<<ag, 256, ATTN_SMEM_BYTES>>>(out);
}